// round 11
// baseline (speedup 1.0000x reference)
#include <cuda_runtime.h>
#include <cuda_bf16.h>
#include <cstdint>

#define TOKENS 16384
#define DIMSZ  4096
#define RNK    128

// ---------------- device scratch ----------------
__device__ float g_H[TOKENS * RNK];   // h = silu(r * x@Wd^T), fp32
__device__ float g_r[TOKENS];         // per-token rms scale

// ---------------- helpers ----------------
__device__ __forceinline__ uint32_t smem_u32(const void* p) {
    uint32_t a;
    asm("{ .reg .u64 t; cvta.to.shared.u64 t, %1; cvt.u32.u64 %0, t; }" : "=r"(a) : "l"(p));
    return a;
}
#define SWZ(b) ((b) ^ (((b) >> 3) & 0x70))

#define PREFETCH_L2(p) asm volatile("prefetch.global.L2 [%0];" :: "l"(p))

__device__ __forceinline__ void ldm4(uint32_t* r, uint32_t addr) {
    asm volatile("ldmatrix.sync.aligned.m8n8.x4.shared.b16 {%0,%1,%2,%3}, [%4];"
                 : "=r"(r[0]), "=r"(r[1]), "=r"(r[2]), "=r"(r[3]) : "r"(addr));
}
__device__ __forceinline__ void mma_bf16(float* d, const uint32_t* a, uint32_t b0, uint32_t b1) {
    asm volatile("mma.sync.aligned.m16n8k16.row.col.f32.bf16.bf16.f32 "
                 "{%0,%1,%2,%3}, {%4,%5,%6,%7}, {%8,%9}, {%0,%1,%2,%3};"
                 : "+f"(d[0]), "+f"(d[1]), "+f"(d[2]), "+f"(d[3])
                 : "r"(a[0]), "r"(a[1]), "r"(a[2]), "r"(a[3]), "r"(b0), "r"(b1));
}

__device__ __forceinline__ uint32_t pack_hilo(float v) {
    __nv_bfloat16 h = __float2bfloat16(v);
    float rem = v - __bfloat162float(h);
    __nv_bfloat16 lo = __float2bfloat16(rem);
    return (uint32_t)__bfloat16_as_ushort(h) | ((uint32_t)__bfloat16_as_ushort(lo) << 16);
}
// split a float4 into packed hi-pair / lo-pair uint2s
__device__ __forceinline__ void split4(float4 v, uint2& hp, uint2& lp) {
    uint32_t p0 = pack_hilo(v.x), p1 = pack_hilo(v.y), p2 = pack_hilo(v.z), p3 = pack_hilo(v.w);
    hp.x = (p0 & 0xffffu) | ((p1 & 0xffffu) << 16);
    hp.y = (p2 & 0xffffu) | ((p3 & 0xffffu) << 16);
    lp.x = (p0 >> 16) | (p1 & 0xffff0000u);
    lp.y = (p2 >> 16) | (p3 & 0xffff0000u);
}

// ---------------- kernel 1 ----------------
// C[16384,128] = X @ Wd^T with fused sumsq; epilogue silu -> g_H (f32) + g_r.
// CTA: M=128 tokens, N=128, K chunks of 64, double-buffered smem,
// f32->bf16 hi/lo split done in-kernel (f32 bytes == hi+lo plane bytes).
// smem/buf (64KB): XH 16K | XL 16K | WH 16K | WL 16K.
static constexpr int SMEM1 = 1024 + 2 * 65536 + 1024;

__global__ __launch_bounds__(256, 1) void k1_rms_gemm(const float* __restrict__ x,
                                                      const float* __restrict__ Wd) {
    extern __shared__ char smem_raw[];
    uint32_t sb = smem_u32(smem_raw);
    uint32_t al = (sb + 1023u) & ~1023u;
    char* sal = smem_raw + (al - sb);

    const uint32_t OFF_SS = 2 * 65536;       // 128 f32 sumsq
    const uint32_t OFF_RV = OFF_SS + 512;    // 128 f32 rv

    int tid = threadIdx.x;
    int wid = tid >> 5;
    int l   = tid & 31;
    int m0  = blockIdx.x * 128;

    if (tid < 128) ((float*)(sal + OFF_SS))[tid] = 0.f;

    // loader mapping: rows it*16 + rsub, 16 float4-cols per 64-wide chunk
    int rsub = tid >> 4;
    int col4 = tid & 15;

    float4 xr[8], wr[8];
    float  ssp[8];
#pragma unroll
    for (int i = 0; i < 8; i++) ssp[i] = 0.f;

    auto loadXW = [&](int c) {
        int k0 = c * 64;
#pragma unroll
        for (int it = 0; it < 8; it++) {
            int row = it * 16 + rsub;
            xr[it] = *(const float4*)(x  + (size_t)(m0 + row) * DIMSZ + k0 + col4 * 4);
            wr[it] = *(const float4*)(Wd + (size_t)row * DIMSZ + k0 + col4 * 4);
        }
    };
    auto storeXW = [&](int buf) {
        uint32_t bufb = (uint32_t)buf * 65536u;
#pragma unroll
        for (int it = 0; it < 8; it++) {
            float4 v = xr[it];
            ssp[it] += v.x * v.x + v.y * v.y + v.z * v.z + v.w * v.w;
            uint32_t so = SWZ((uint32_t)(it * 16 + rsub) * 128 + (uint32_t)col4 * 8);
            uint2 hp, lp;
            split4(v, hp, lp);
            *(uint2*)(sal + bufb + so) = hp;             // XH
            *(uint2*)(sal + bufb + 16384 + so) = lp;     // XL
            split4(wr[it], hp, lp);
            *(uint2*)(sal + bufb + 32768 + so) = hp;     // WH
            *(uint2*)(sal + bufb + 49152 + so) = lp;     // WL
        }
    };

    // warp tiles: 4 (M) x 2 (N); warp tile 32x64
    int wm0 = (wid & 3) * 32;
    int wn0 = (wid >> 2) * 64;

    uint32_t a_row = (uint32_t)(l & 15);
    uint32_t a_kb  = (uint32_t)((l >> 4) * 16);
    uint32_t lx    = (uint32_t)((l & 7) * 16);
    uint32_t b_row = (uint32_t)((l >> 4) * 8 + (l & 7));
    uint32_t b_kb  = (uint32_t)(((l >> 3) & 1) * 16);

    float acc[2][8][4];
#pragma unroll
    for (int mt = 0; mt < 2; mt++)
#pragma unroll
        for (int nt = 0; nt < 8; nt++)
#pragma unroll
            for (int j = 0; j < 4; j++) acc[mt][nt][j] = 0.f;

    // prologue
    loadXW(0);
    storeXW(0);
    __syncthreads();

    for (int c = 0; c < 64; c++) {
        int buf = c & 1;
        if (c < 63) loadXW(c + 1);   // LDGs in flight during MMA

        uint32_t bufb = al + (uint32_t)buf * 65536u;
#pragma unroll
        for (int ks = 0; ks < 4; ks++) {
            uint32_t kso = (uint32_t)ks * 32;
            uint32_t ah[2][4], alo[2][4];
#pragma unroll
            for (int mt = 0; mt < 2; mt++) {
                uint32_t ro = ((uint32_t)(wm0 + mt * 16) + a_row) * 128;
                uint32_t ko = (kso + a_kb) ^ lx;
                ldm4(ah[mt],  bufb + ro + ko);
                ldm4(alo[mt], bufb + 16384 + ro + ko);
            }
            uint32_t bh[4][4], bl[4][4];
#pragma unroll
            for (int pr = 0; pr < 4; pr++) {
                uint32_t ro = ((uint32_t)(wn0 + pr * 16) + b_row) * 128;
                uint32_t ko = (kso + b_kb) ^ lx;
                ldm4(bh[pr], bufb + 32768 + ro + ko);
                ldm4(bl[pr], bufb + 49152 + ro + ko);
            }
#pragma unroll
            for (int mt = 0; mt < 2; mt++)
#pragma unroll
                for (int nt = 0; nt < 8; nt++) {
                    int pr = nt >> 1, of = (nt & 1) * 2;
                    mma_bf16(acc[mt][nt], ah[mt],  bh[pr][of], bh[pr][of + 1]);
                    mma_bf16(acc[mt][nt], ah[mt],  bl[pr][of], bl[pr][of + 1]);
                    mma_bf16(acc[mt][nt], alo[mt], bh[pr][of], bh[pr][of + 1]);
                }
        }
        if (c < 63) storeXW(buf ^ 1);
        __syncthreads();
    }

    // ---- sumsq reduce -> rv ----
#pragma unroll
    for (int it = 0; it < 8; it++)
        atomicAdd(((float*)(sal + OFF_SS)) + it * 16 + rsub, ssp[it]);
    __syncthreads();
    if (tid < 128) {
        float rv = rsqrtf(((float*)(sal + OFF_SS))[tid] * (1.0f / 4096.0f) + 1.1920929e-7f);
        ((float*)(sal + OFF_RV))[tid] = rv;
        g_r[m0 + tid] = rv;
    }
    __syncthreads();

    // ---- epilogue: h = silu(rv*acc) -> g_H (f32) ----
    const float* RV = (const float*)(sal + OFF_RV);
#pragma unroll
    for (int mt = 0; mt < 2; mt++) {
#pragma unroll
        for (int rh = 0; rh < 2; rh++) {
            int row = wm0 + mt * 16 + rh * 8 + (l >> 2);
            float rv = RV[row];
#pragma unroll
            for (int nt = 0; nt < 8; nt++) {
                int col = wn0 + nt * 8 + 2 * (l & 3);
                float z0 = acc[mt][nt][rh * 2 + 0] * rv;
                float z1 = acc[mt][nt][rh * 2 + 1] * rv;
                float2 h;
                h.x = z0 / (1.0f + __expf(-z0));
                h.y = z1 / (1.0f + __expf(-z1));
                *(float2*)(g_H + (size_t)(m0 + row) * RNK + col) = h;
            }
        }
    }
}

// ---------------- kernel 2 ----------------
// out = x * r * sigmoid(H @ Wu^T). CTA: M=128 tokens x N=128 dims, K=128
// in 2 chunks of 64 (chunk-1 LDGs overlap chunk-0 MMAs).
// smem: AH 32K | AL 32K | BH 32K | BL 32K, each [kchunk(2)][row(128)][128B].
static constexpr int SMEM2 = 1024 + 131072 + 1024;

__global__ __launch_bounds__(256, 1) void k2_gate(const float* __restrict__ x,
                                                  const float* __restrict__ Wu,
                                                  float* __restrict__ out) {
    extern __shared__ char smem_raw[];
    uint32_t sb = smem_u32(smem_raw);
    uint32_t al = (sb + 1023u) & ~1023u;
    char* sal = smem_raw + (al - sb);
    const uint32_t OFF_RV = 131072;

    int tid = threadIdx.x;
    int wid = tid >> 5;
    int l   = tid & 31;
    int m0  = blockIdx.y * 128;
    int d0  = blockIdx.x * 128;

    // warm L2 with this CTA's x tile (used only in the epilogue)
    {
        const char* xb = (const char*)(x + (size_t)m0 * DIMSZ + d0);
#pragma unroll
        for (int j = 0; j < 2; j++) {
            int line = tid * 2 + j;          // 512 lines of 128B
            int row = line >> 2;
            PREFETCH_L2(xb + (size_t)row * (DIMSZ * 4) + (line & 3) * 128);
        }
    }

    // loader mapping: per chunk, per operand: 128 rows x 16 float4
    int rrow = tid >> 1;                      // 0..127
    int rc4h = (tid & 1) * 8;                 // float4 col base (0 or 8)

    float4 ar[8], br[8];
    auto loadAB = [&](int kc) {
        int k0 = kc * 64;
#pragma unroll
        for (int i = 0; i < 8; i++) {
            int c4 = rc4h + (i & 7);
            ar[i] = *(const float4*)(g_H + (size_t)(m0 + rrow) * RNK + k0 + c4 * 4);
            br[i] = *(const float4*)(Wu  + (size_t)(d0 + rrow) * RNK + k0 + c4 * 4);
        }
    };
    auto storeAB = [&](int kc) {
        uint32_t cb = (uint32_t)kc * 16384u;
#pragma unroll
        for (int i = 0; i < 8; i++) {
            int c4 = rc4h + (i & 7);
            uint32_t so = SWZ((uint32_t)rrow * 128 + (uint32_t)c4 * 8);
            uint2 hp, lp;
            split4(ar[i], hp, lp);
            *(uint2*)(sal + cb + so) = hp;              // AH
            *(uint2*)(sal + 32768 + cb + so) = lp;      // AL
            split4(br[i], hp, lp);
            *(uint2*)(sal + 65536 + cb + so) = hp;      // BH
            *(uint2*)(sal + 98304 + cb + so) = lp;      // BL
        }
    };

    if (tid < 128) ((float*)(sal + OFF_RV))[tid] = g_r[m0 + tid];

    loadAB(0);
    storeAB(0);
    loadAB(1);            // chunk-1 LDGs fly during sync + chunk-0 MMAs
    __syncthreads();

    // warp tiles: 2(M) x 4(N); warp tile 64x32
    int wm0 = (wid & 1) * 64;
    int wn0 = (wid >> 1) * 32;

    uint32_t a_row = (uint32_t)(l & 15);
    uint32_t a_kb  = (uint32_t)((l >> 4) * 16);
    uint32_t lx    = (uint32_t)((l & 7) * 16);
    uint32_t b_row = (uint32_t)((l >> 4) * 8 + (l & 7));
    uint32_t b_kb  = (uint32_t)(((l >> 3) & 1) * 16);

    float acc[4][4][4];
#pragma unroll
    for (int mt = 0; mt < 4; mt++)
#pragma unroll
        for (int nt = 0; nt < 4; nt++)
#pragma unroll
            for (int j = 0; j < 4; j++) acc[mt][nt][j] = 0.f;

#pragma unroll
    for (int kc = 0; kc < 2; kc++) {
        uint32_t cb = (uint32_t)kc * 16384u;
#pragma unroll
        for (int ks = 0; ks < 4; ks++) {
            uint32_t kso = (uint32_t)ks * 32;
            uint32_t ah[4][4], alo[4][4];
#pragma unroll
            for (int mt = 0; mt < 4; mt++) {
                uint32_t ro = ((uint32_t)(wm0 + mt * 16) + a_row) * 128;
                uint32_t ko = (kso + a_kb) ^ lx;
                ldm4(ah[mt],  al + cb + ro + ko);
                ldm4(alo[mt], al + 32768 + cb + ro + ko);
            }
            uint32_t bh[2][4], bl[2][4];
#pragma unroll
            for (int pr = 0; pr < 2; pr++) {
                uint32_t ro = ((uint32_t)(wn0 + pr * 16) + b_row) * 128;
                uint32_t ko = (kso + b_kb) ^ lx;
                ldm4(bh[pr], al + 65536 + cb + ro + ko);
                ldm4(bl[pr], al + 98304 + cb + ro + ko);
            }
#pragma unroll
            for (int mt = 0; mt < 4; mt++)
#pragma unroll
                for (int nt = 0; nt < 4; nt++) {
                    int pr = nt >> 1, of = (nt & 1) * 2;
                    mma_bf16(acc[mt][nt], ah[mt],  bh[pr][of], bh[pr][of + 1]);
                    mma_bf16(acc[mt][nt], ah[mt],  bl[pr][of], bl[pr][of + 1]);
                    mma_bf16(acc[mt][nt], alo[mt], bh[pr][of], bh[pr][of + 1]);
                }
        }
        if (kc == 0) {
            // publish chunk 1 (its LDGs were issued before chunk-0 MMAs)
            storeAB(1);
            __syncthreads();
        }
    }

    // ---- epilogue: out = x * rv * sigmoid(acc); streaming stores ----
    const float* RV = (const float*)(sal + OFF_RV);
#pragma unroll
    for (int mt = 0; mt < 4; mt++) {
#pragma unroll
        for (int rh = 0; rh < 2; rh++) {
            int row = wm0 + mt * 16 + rh * 8 + (l >> 2);
            float rv = RV[row];
#pragma unroll
            for (int nt = 0; nt < 4; nt++) {
                int col = d0 + wn0 + nt * 8 + 2 * (l & 3);
                float z0 = acc[mt][nt][rh * 2 + 0];
                float z1 = acc[mt][nt][rh * 2 + 1];
                float g0 = 1.0f / (1.0f + __expf(-z0));
                float g1 = 1.0f / (1.0f + __expf(-z1));
                size_t o = (size_t)(m0 + row) * DIMSZ + col;
                float2 xv = *(const float2*)(x + o);
                float2 ov;
                ov.x = xv.x * rv * g0;
                ov.y = xv.y * rv * g1;
                __stcs((float2*)(out + o), ov);   // evict-first: out never re-read
            }
        }
    }
}

// ---------------- launch ----------------
extern "C" void kernel_launch(void* const* d_in, const int* in_sizes, int n_in,
                              void* d_out, int out_size) {
    const float* x  = (const float*)d_in[0];
    const float* Wd = (const float*)d_in[1];
    const float* Wu = (const float*)d_in[2];
    float* out = (float*)d_out;

    cudaFuncSetAttribute(k1_rms_gemm, cudaFuncAttributeMaxDynamicSharedMemorySize, SMEM1);
    cudaFuncSetAttribute(k2_gate,     cudaFuncAttributeMaxDynamicSharedMemorySize, SMEM2);

    k1_rms_gemm<<<TOKENS / 128, 256, SMEM1>>>(x, Wd);
    k2_gate<<<dim3(DIMSZ / 128, TOKENS / 128), 256, SMEM2>>>(x, Wu, out);
}

// round 12
// speedup vs baseline: 1.6203x; 1.6203x over previous
#include <cuda_runtime.h>
#include <cuda_bf16.h>
#include <cstdint>

#define TOKENS 16384
#define DIMSZ  4096
#define RNK    128

// ---------------- device scratch ----------------
__device__ __nv_bfloat16 g_Wd_hi[RNK * DIMSZ];
__device__ __nv_bfloat16 g_Wd_lo[RNK * DIMSZ];
__device__ __nv_bfloat16 g_Wu_hi[DIMSZ * RNK];
__device__ __nv_bfloat16 g_Wu_lo[DIMSZ * RNK];
__device__ __nv_bfloat16 g_H_hi [TOKENS * RNK];
__device__ __nv_bfloat16 g_H_lo [TOKENS * RNK];
__device__ float         g_r    [TOKENS];

// ---------------- helpers ----------------
__device__ __forceinline__ uint32_t smem_u32(const void* p) {
    uint32_t a;
    asm("{ .reg .u64 t; cvta.to.shared.u64 t, %1; cvt.u32.u64 %0, t; }" : "=r"(a) : "l"(p));
    return a;
}
#define SWZ(b) ((b) ^ (((b) >> 3) & 0x70))

#define PREFETCH_L2(p) asm volatile("prefetch.global.L2 [%0];" :: "l"(p))
#define CP_ASYNC16(dst, src) \
    asm volatile("cp.async.cg.shared.global [%0], [%1], 16;" :: "r"(dst), "l"(src))
#define CP_COMMIT() asm volatile("cp.async.commit_group;" ::: "memory")
#define CP_WAIT0()  asm volatile("cp.async.wait_group 0;" ::: "memory")

__device__ __forceinline__ void ldm4(uint32_t* r, uint32_t addr) {
    asm volatile("ldmatrix.sync.aligned.m8n8.x4.shared.b16 {%0,%1,%2,%3}, [%4];"
                 : "=r"(r[0]), "=r"(r[1]), "=r"(r[2]), "=r"(r[3]) : "r"(addr));
}
__device__ __forceinline__ void mma_bf16(float* d, const uint32_t* a, uint32_t b0, uint32_t b1) {
    asm volatile("mma.sync.aligned.m16n8k16.row.col.f32.bf16.bf16.f32 "
                 "{%0,%1,%2,%3}, {%4,%5,%6,%7}, {%8,%9}, {%0,%1,%2,%3};"
                 : "+f"(d[0]), "+f"(d[1]), "+f"(d[2]), "+f"(d[3])
                 : "r"(a[0]), "r"(a[1]), "r"(a[2]), "r"(a[3]), "r"(b0), "r"(b1));
}

__device__ __forceinline__ uint32_t pack_hilo(float v) {
    __nv_bfloat16 h = __float2bfloat16(v);
    float rem = v - __bfloat162float(h);
    __nv_bfloat16 lo = __float2bfloat16(rem);
    return (uint32_t)__bfloat16_as_ushort(h) | ((uint32_t)__bfloat16_as_ushort(lo) << 16);
}
__device__ __forceinline__ void split4(float4 v, uint2& hp, uint2& lp) {
    uint32_t p0 = pack_hilo(v.x), p1 = pack_hilo(v.y), p2 = pack_hilo(v.z), p3 = pack_hilo(v.w);
    hp.x = (p0 & 0xffffu) | ((p1 & 0xffffu) << 16);
    hp.y = (p2 & 0xffffu) | ((p3 & 0xffffu) << 16);
    lp.x = (p0 >> 16) | (p1 & 0xffff0000u);
    lp.y = (p2 >> 16) | (p3 & 0xffff0000u);
}
__device__ __forceinline__ void bfsplit(float v, uint16_t& h, uint16_t& l) {
    __nv_bfloat16 bh = __float2bfloat16(v);
    float r = v - __bfloat162float(bh);
    h = __bfloat16_as_ushort(bh);
    l = __bfloat16_as_ushort(__float2bfloat16(r));
}

// ---------------- kernel 0: split weights into hi/lo planes ----------------
__global__ void kprep(const float* __restrict__ Wd, const float* __restrict__ Wu) {
    int i = blockIdx.x * blockDim.x + threadIdx.x;
    uint16_t h, l;
    if (i < RNK * DIMSZ) {
        bfsplit(Wd[i], h, l);
        g_Wd_hi[i] = __ushort_as_bfloat16(h);
        g_Wd_lo[i] = __ushort_as_bfloat16(l);
    } else {
        int j = i - RNK * DIMSZ;
        bfsplit(Wu[j], h, l);
        g_Wu_hi[j] = __ushort_as_bfloat16(h);
        g_Wu_lo[j] = __ushort_as_bfloat16(l);
    }
}

// ---------------- kernel 1 ----------------
// X @ Wd^T fused with sumsq; epilogue silu -> H hi/lo planes + g_r.
// 512 threads, M=128, N=128, K chunks of 64, double-buffered.
// smem/buf 64KB: XH 16K | XL 16K | WH 16K | WL 16K.
static constexpr int SMEM1 = 1024 + 2 * 65536 + 1024;

__global__ __launch_bounds__(512, 1) void k1_rms_gemm(const float* __restrict__ x) {
    extern __shared__ char smem_raw[];
    uint32_t sb = smem_u32(smem_raw);
    uint32_t al = (sb + 1023u) & ~1023u;
    char* sal = smem_raw + (al - sb);

    const uint32_t OFF_SS = 2 * 65536;
    const uint32_t OFF_RV = OFF_SS + 512;

    int tid = threadIdx.x;
    int wid = tid >> 5;
    int l   = tid & 31;
    int m0  = blockIdx.x * 128;

    if (tid < 128) ((float*)(sal + OFF_SS))[tid] = 0.f;

    // X loader: rows it*32 + rsub (it<4), 16 float4-cols
    int rsub = tid >> 4;     // 0..31
    int col4 = tid & 15;

    float4 xr[4];
    float  ssp[4];
#pragma unroll
    for (int i = 0; i < 4; i++) ssp[i] = 0.f;

    auto loadX = [&](int c) {
        int k0 = c * 64;
#pragma unroll
        for (int it = 0; it < 4; it++) {
            int row = it * 32 + rsub;
            xr[it] = *(const float4*)(x + (size_t)(m0 + row) * DIMSZ + k0 + col4 * 4);
        }
    };
    auto storeX = [&](int buf) {
        uint32_t bufb = (uint32_t)buf * 65536u;
#pragma unroll
        for (int it = 0; it < 4; it++) {
            float4 v = xr[it];
            ssp[it] += v.x * v.x + v.y * v.y + v.z * v.z + v.w * v.w;
            uint32_t so = SWZ((uint32_t)(it * 32 + rsub) * 128 + (uint32_t)col4 * 8);
            uint2 hp, lp;
            split4(v, hp, lp);
            *(uint2*)(sal + bufb + so) = hp;             // XH
            *(uint2*)(sal + bufb + 16384 + so) = lp;     // XL
        }
    };
    auto loadW = [&](int c, int buf) {
        uint32_t bufb = (uint32_t)buf * 65536u;
        int k0 = c * 64;
#pragma unroll
        for (int i = 0; i < 4; i++) {
            int idx = tid + i * 512;             // 0..2047
            int plane = idx >> 10;               // 0=hi,1=lo
            int rem = idx & 1023;
            int row = rem >> 3;
            int ci  = rem & 7;
            const char* src = (const char*)(plane ? g_Wd_lo : g_Wd_hi)
                              + (size_t)row * (DIMSZ * 2) + (size_t)k0 * 2 + ci * 16;
            uint32_t dst = al + bufb + 32768 + (uint32_t)plane * 16384
                           + SWZ((uint32_t)row * 128 + (uint32_t)ci * 16);
            CP_ASYNC16(dst, src);
        }
    };

    // 16 warps: 4(M) x 4(N), warp tile 32x32
    int wm0 = (wid & 3) * 32;
    int wn0 = (wid >> 2) * 32;

    uint32_t a_row = (uint32_t)(l & 15);
    uint32_t a_kb  = (uint32_t)((l >> 4) * 16);
    uint32_t lx    = (uint32_t)((l & 7) * 16);
    uint32_t b_row = (uint32_t)((l >> 4) * 8 + (l & 7));
    uint32_t b_kb  = (uint32_t)(((l >> 3) & 1) * 16);

    float acc[2][4][4];
#pragma unroll
    for (int mt = 0; mt < 2; mt++)
#pragma unroll
        for (int nt = 0; nt < 4; nt++)
#pragma unroll
            for (int j = 0; j < 4; j++) acc[mt][nt][j] = 0.f;

    // prologue
    loadX(0);
    storeX(0);
    loadW(0, 0);
    CP_COMMIT();
    loadX(1);

    for (int c = 0; c < 64; c++) {
        int buf = c & 1;
        CP_WAIT0();
        __syncthreads();
        if (c < 63) {
            loadW(c + 1, buf ^ 1);
            CP_COMMIT();
            storeX(buf ^ 1);
        }
        if (c < 62) loadX(c + 2);

        uint32_t bufb = al + (uint32_t)buf * 65536u;
#pragma unroll
        for (int ks = 0; ks < 4; ks++) {
            uint32_t kso = (uint32_t)ks * 32;
            uint32_t ah[2][4], alo[2][4];
#pragma unroll
            for (int mt = 0; mt < 2; mt++) {
                uint32_t ro = ((uint32_t)(wm0 + mt * 16) + a_row) * 128;
                uint32_t ko = (kso + a_kb) ^ lx;
                ldm4(ah[mt],  bufb + ro + ko);
                ldm4(alo[mt], bufb + 16384 + ro + ko);
            }
            uint32_t bh[2][4], bl[2][4];
#pragma unroll
            for (int pr = 0; pr < 2; pr++) {
                uint32_t ro = ((uint32_t)(wn0 + pr * 16) + b_row) * 128;
                uint32_t ko = (kso + b_kb) ^ lx;
                ldm4(bh[pr], bufb + 32768 + ro + ko);
                ldm4(bl[pr], bufb + 49152 + ro + ko);
            }
#pragma unroll
            for (int mt = 0; mt < 2; mt++)
#pragma unroll
                for (int nt = 0; nt < 4; nt++) {
                    int pr = nt >> 1, of = (nt & 1) * 2;
                    mma_bf16(acc[mt][nt], ah[mt],  bh[pr][of], bh[pr][of + 1]);
                    mma_bf16(acc[mt][nt], ah[mt],  bl[pr][of], bl[pr][of + 1]);
                    mma_bf16(acc[mt][nt], alo[mt], bh[pr][of], bh[pr][of + 1]);
                }
        }
    }

    // ---- sumsq reduce -> rv ----
#pragma unroll
    for (int it = 0; it < 4; it++)
        atomicAdd(((float*)(sal + OFF_SS)) + it * 32 + rsub, ssp[it]);
    __syncthreads();
    if (tid < 128) {
        float rv = rsqrtf(((float*)(sal + OFF_SS))[tid] * (1.0f / 4096.0f) + 1.1920929e-7f);
        ((float*)(sal + OFF_RV))[tid] = rv;
        g_r[m0 + tid] = rv;
    }
    __syncthreads();

    // ---- epilogue: h = silu(rv*acc) -> H hi/lo planes ----
    const float* RV = (const float*)(sal + OFF_RV);
#pragma unroll
    for (int mt = 0; mt < 2; mt++) {
#pragma unroll
        for (int rh = 0; rh < 2; rh++) {
            int row = wm0 + mt * 16 + rh * 8 + (l >> 2);
            float rv = RV[row];
#pragma unroll
            for (int nt = 0; nt < 4; nt++) {
                int col = wn0 + nt * 8 + 2 * (l & 3);
                float z0 = acc[mt][nt][rh * 2 + 0] * rv;
                float z1 = acc[mt][nt][rh * 2 + 1] * rv;
                float h0 = z0 / (1.0f + __expf(-z0));
                float h1 = z1 / (1.0f + __expf(-z1));
                uint32_t p0 = pack_hilo(h0), p1 = pack_hilo(h1);
                size_t o2 = ((size_t)(m0 + row) * RNK + col) * 2;
                *(uint32_t*)((char*)g_H_hi + o2) = (p0 & 0xffffu) | ((p1 & 0xffffu) << 16);
                *(uint32_t*)((char*)g_H_lo + o2) = (p0 >> 16) | (p1 & 0xffff0000u);
            }
        }
    }
}

// ---------------- kernel 2 ----------------
// out = x * r * sigmoid(H @ Wu^T). 512 threads, M=128 x N=128, K=128.
// All operands via cp.async (no staging registers).
// smem: AH 32K | AL 32K | BH 32K | BL 32K, each [kchunk(2)][row(128)][128B].
static constexpr int SMEM2 = 1024 + 131072 + 1024;

__global__ __launch_bounds__(512, 1) void k2_gate(const float* __restrict__ x,
                                                  float* __restrict__ out) {
    extern __shared__ char smem_raw[];
    uint32_t sb = smem_u32(smem_raw);
    uint32_t al = (sb + 1023u) & ~1023u;
    char* sal = smem_raw + (al - sb);
    const uint32_t OFF_RV = 131072;

    int tid = threadIdx.x;
    int wid = tid >> 5;
    int l   = tid & 31;
    int m0  = blockIdx.y * 128;
    int d0  = blockIdx.x * 128;

    // issue all operand cp.asyncs: 8192 16B chunks, 16/thread
#pragma unroll
    for (int i = 0; i < 16; i++) {
        int idx = tid + i * 512;
        int operand = idx >> 12;          // 0=A(H), 1=B(Wu)
        int plane = (idx >> 11) & 1;      // 0=hi,1=lo
        int rem = idx & 2047;
        int row = rem >> 4;
        int ci  = rem & 15;
        const char* base;
        size_t srow;
        if (operand == 0) {
            base = (const char*)(plane ? g_H_lo : g_H_hi);
            srow = (size_t)(m0 + row);
        } else {
            base = (const char*)(plane ? g_Wu_lo : g_Wu_hi);
            srow = (size_t)(d0 + row);
        }
        const char* src = base + srow * 256 + ci * 16;
        uint32_t dst = al + (uint32_t)operand * 65536 + (uint32_t)plane * 32768
                       + (uint32_t)(ci >> 3) * 16384
                       + SWZ((uint32_t)row * 128 + (uint32_t)(ci & 7) * 16);
        CP_ASYNC16(dst, src);
    }
    CP_COMMIT();

    // warm L2 with this CTA's x tile (epilogue-only data); 512 x 128B lines
    {
        const char* xb = (const char*)(x + (size_t)m0 * DIMSZ + d0);
        int row = tid >> 2;
        PREFETCH_L2(xb + (size_t)row * (DIMSZ * 4) + (tid & 3) * 128);
    }

    if (tid < 128) ((float*)(sal + OFF_RV))[tid] = g_r[m0 + tid];

    // 16 warps: 4(M) x 4(N), warp tile 32x32
    int wm0 = (wid & 3) * 32;
    int wn0 = (wid >> 2) * 32;

    uint32_t a_row = (uint32_t)(l & 15);
    uint32_t a_kb  = (uint32_t)((l >> 4) * 16);
    uint32_t lx    = (uint32_t)((l & 7) * 16);
    uint32_t b_row = (uint32_t)((l >> 4) * 8 + (l & 7));
    uint32_t b_kb  = (uint32_t)(((l >> 3) & 1) * 16);

    float acc[2][4][4];
#pragma unroll
    for (int mt = 0; mt < 2; mt++)
#pragma unroll
        for (int nt = 0; nt < 4; nt++)
#pragma unroll
            for (int j = 0; j < 4; j++) acc[mt][nt][j] = 0.f;

    CP_WAIT0();
    __syncthreads();

#pragma unroll
    for (int kc = 0; kc < 2; kc++) {
        uint32_t cb = (uint32_t)kc * 16384u;
#pragma unroll
        for (int ks = 0; ks < 4; ks++) {
            uint32_t kso = (uint32_t)ks * 32;
            uint32_t ah[2][4], alo[2][4];
#pragma unroll
            for (int mt = 0; mt < 2; mt++) {
                uint32_t ro = ((uint32_t)(wm0 + mt * 16) + a_row) * 128;
                uint32_t ko = (kso + a_kb) ^ lx;
                ldm4(ah[mt],  al + cb + ro + ko);
                ldm4(alo[mt], al + 32768 + cb + ro + ko);
            }
            uint32_t bh[2][4], bl[2][4];
#pragma unroll
            for (int pr = 0; pr < 2; pr++) {
                uint32_t ro = ((uint32_t)(wn0 + pr * 16) + b_row) * 128;
                uint32_t ko = (kso + b_kb) ^ lx;
                ldm4(bh[pr], al + 65536 + cb + ro + ko);
                ldm4(bl[pr], al + 98304 + cb + ro + ko);
            }
#pragma unroll
            for (int mt = 0; mt < 2; mt++)
#pragma unroll
                for (int nt = 0; nt < 4; nt++) {
                    int pr = nt >> 1, of = (nt & 1) * 2;
                    mma_bf16(acc[mt][nt], ah[mt],  bh[pr][of], bh[pr][of + 1]);
                    mma_bf16(acc[mt][nt], ah[mt],  bl[pr][of], bl[pr][of + 1]);
                    mma_bf16(acc[mt][nt], alo[mt], bh[pr][of], bh[pr][of + 1]);
                }
        }
    }

    // ---- epilogue: out = x * rv * sigmoid(acc); streaming stores ----
    const float* RV = (const float*)(sal + OFF_RV);
#pragma unroll
    for (int mt = 0; mt < 2; mt++) {
#pragma unroll
        for (int rh = 0; rh < 2; rh++) {
            int row = wm0 + mt * 16 + rh * 8 + (l >> 2);
            float rv = RV[row];
#pragma unroll
            for (int nt = 0; nt < 4; nt++) {
                int col = d0 + wn0 + nt * 8 + 2 * (l & 3);
                float z0 = acc[mt][nt][rh * 2 + 0];
                float z1 = acc[mt][nt][rh * 2 + 1];
                float g0 = 1.0f / (1.0f + __expf(-z0));
                float g1 = 1.0f / (1.0f + __expf(-z1));
                size_t o = (size_t)(m0 + row) * DIMSZ + col;
                float2 xv = *(const float2*)(x + o);
                float2 ov;
                ov.x = xv.x * rv * g0;
                ov.y = xv.y * rv * g1;
                __stcs((float2*)(out + o), ov);
            }
        }
    }
}

// ---------------- launch ----------------
extern "C" void kernel_launch(void* const* d_in, const int* in_sizes, int n_in,
                              void* d_out, int out_size) {
    const float* x  = (const float*)d_in[0];
    const float* Wd = (const float*)d_in[1];
    const float* Wu = (const float*)d_in[2];
    float* out = (float*)d_out;

    cudaFuncSetAttribute(k1_rms_gemm, cudaFuncAttributeMaxDynamicSharedMemorySize, SMEM1);
    cudaFuncSetAttribute(k2_gate,     cudaFuncAttributeMaxDynamicSharedMemorySize, SMEM2);

    kprep<<<(2 * RNK * DIMSZ) / 256, 256>>>(Wd, Wu);
    k1_rms_gemm<<<TOKENS / 128, 512, SMEM1>>>(x);
    k2_gate<<<dim3(DIMSZ / 128, TOKENS / 128), 512, SMEM2>>>(x, out);
}

// round 17
// speedup vs baseline: 1.7968x; 1.1090x over previous
#include <cuda_runtime.h>
#include <cuda_bf16.h>
#include <cstdint>

#define TOKENS 16384
#define DIMSZ  4096
#define RNK    128

// ---------------- device scratch ----------------
__device__ __nv_bfloat16 g_Wd_hi[RNK * DIMSZ];
__device__ __nv_bfloat16 g_Wd_lo[RNK * DIMSZ];
__device__ __nv_bfloat16 g_Wu_hi[DIMSZ * RNK];
__device__ __nv_bfloat16 g_Wu_lo[DIMSZ * RNK];
__device__ __nv_bfloat16 g_H_hi [TOKENS * RNK];
__device__ __nv_bfloat16 g_H_lo [TOKENS * RNK];
__device__ float         g_r    [TOKENS];

// ---------------- helpers ----------------
__device__ __forceinline__ uint32_t smem_u32(const void* p) {
    uint32_t a;
    asm("{ .reg .u64 t; cvta.to.shared.u64 t, %1; cvt.u32.u64 %0, t; }" : "=r"(a) : "l"(p));
    return a;
}
#define SWZ(b) ((b) ^ (((b) >> 3) & 0x70))

#define PREFETCH_L2(p) asm volatile("prefetch.global.L2 [%0];" :: "l"(p))
#define CP_ASYNC16(dst, src) \
    asm volatile("cp.async.cg.shared.global [%0], [%1], 16;" :: "r"(dst), "l"(src))
#define CP_COMMIT() asm volatile("cp.async.commit_group;" ::: "memory")
#define CP_WAIT0()  asm volatile("cp.async.wait_group 0;" ::: "memory")

__device__ __forceinline__ void ldm4(uint32_t* r, uint32_t addr) {
    asm volatile("ldmatrix.sync.aligned.m8n8.x4.shared.b16 {%0,%1,%2,%3}, [%4];"
                 : "=r"(r[0]), "=r"(r[1]), "=r"(r[2]), "=r"(r[3]) : "r"(addr));
}
__device__ __forceinline__ void mma_bf16(float* d, const uint32_t* a, uint32_t b0, uint32_t b1) {
    asm volatile("mma.sync.aligned.m16n8k16.row.col.f32.bf16.bf16.f32 "
                 "{%0,%1,%2,%3}, {%4,%5,%6,%7}, {%8,%9}, {%0,%1,%2,%3};"
                 : "+f"(d[0]), "+f"(d[1]), "+f"(d[2]), "+f"(d[3])
                 : "r"(a[0]), "r"(a[1]), "r"(a[2]), "r"(a[3]), "r"(b0), "r"(b1));
}

__device__ __forceinline__ uint32_t pack_hilo(float v) {
    __nv_bfloat16 h = __float2bfloat16(v);
    float rem = v - __bfloat162float(h);
    __nv_bfloat16 lo = __float2bfloat16(rem);
    return (uint32_t)__bfloat16_as_ushort(h) | ((uint32_t)__bfloat16_as_ushort(lo) << 16);
}
__device__ __forceinline__ void split4(float4 v, uint2& hp, uint2& lp) {
    uint32_t p0 = pack_hilo(v.x), p1 = pack_hilo(v.y), p2 = pack_hilo(v.z), p3 = pack_hilo(v.w);
    hp.x = (p0 & 0xffffu) | ((p1 & 0xffffu) << 16);
    hp.y = (p2 & 0xffffu) | ((p3 & 0xffffu) << 16);
    lp.x = (p0 >> 16) | (p1 & 0xffff0000u);
    lp.y = (p2 >> 16) | (p3 & 0xffff0000u);
}
__device__ __forceinline__ void bfsplit(float v, uint16_t& h, uint16_t& l) {
    __nv_bfloat16 bh = __float2bfloat16(v);
    float r = v - __bfloat162float(bh);
    h = __bfloat16_as_ushort(bh);
    l = __bfloat16_as_ushort(__float2bfloat16(r));
}

// ---------------- kernel 0: split weights into hi/lo planes ----------------
__global__ void kprep(const float* __restrict__ Wd, const float* __restrict__ Wu) {
    int i = blockIdx.x * blockDim.x + threadIdx.x;
    uint16_t h, l;
    if (i < RNK * DIMSZ) {
        bfsplit(Wd[i], h, l);
        g_Wd_hi[i] = __ushort_as_bfloat16(h);
        g_Wd_lo[i] = __ushort_as_bfloat16(l);
    } else {
        int j = i - RNK * DIMSZ;
        bfsplit(Wu[j], h, l);
        g_Wu_hi[j] = __ushort_as_bfloat16(h);
        g_Wu_lo[j] = __ushort_as_bfloat16(l);
    }
}

// ---------------- kernel 1 ----------------
// X @ Wd^T fused with sumsq; epilogue silu -> H hi/lo planes + g_r.
// 256 threads, M=64 tokens, N=128, K chunks of 64, double-buffered, 2 CTA/SM.
// smem/buf 48KB: XH 8K | XL 8K | WH 16K | WL 16K.
static constexpr int SMEM1 = 1024 + 2 * 49152 + 1024;

__global__ __launch_bounds__(256, 2) void k1_rms_gemm(const float* __restrict__ x) {
    extern __shared__ char smem_raw[];
    uint32_t sb = smem_u32(smem_raw);
    uint32_t al = (sb + 1023u) & ~1023u;
    char* sal = smem_raw + (al - sb);

    const uint32_t OFF_SS = 2 * 49152;         // 64 f32 sumsq
    const uint32_t OFF_RV = OFF_SS + 256;      // 64 f32 rv

    int tid = threadIdx.x;
    int wid = tid >> 5;
    int l   = tid & 31;
    int m0  = blockIdx.x * 64;

    if (tid < 64) ((float*)(sal + OFF_SS))[tid] = 0.f;

    // X loader: rows it*16 + rsub (it<4), 16 float4-cols
    int rsub = tid >> 4;     // 0..15
    int col4 = tid & 15;

    float4 xr[4];
    float  ssp[4];
#pragma unroll
    for (int i = 0; i < 4; i++) ssp[i] = 0.f;

    auto loadX = [&](int c) {
        int k0 = c * 64;
#pragma unroll
        for (int it = 0; it < 4; it++) {
            int row = it * 16 + rsub;
            xr[it] = *(const float4*)(x + (size_t)(m0 + row) * DIMSZ + k0 + col4 * 4);
        }
    };
    auto storeX = [&](int buf) {
        uint32_t bufb = (uint32_t)buf * 49152u;
#pragma unroll
        for (int it = 0; it < 4; it++) {
            float4 v = xr[it];
            ssp[it] += v.x * v.x + v.y * v.y + v.z * v.z + v.w * v.w;
            uint32_t so = SWZ((uint32_t)(it * 16 + rsub) * 128 + (uint32_t)col4 * 8);
            uint2 hp, lp;
            split4(v, hp, lp);
            *(uint2*)(sal + bufb + so) = hp;             // XH
            *(uint2*)(sal + bufb + 8192 + so) = lp;      // XL
        }
    };
    auto loadW = [&](int c, int buf) {
        uint32_t bufb = (uint32_t)buf * 49152u;
        int k0 = c * 64;
#pragma unroll
        for (int i = 0; i < 8; i++) {
            int idx = tid + i * 256;             // 0..2047
            int plane = idx >> 10;               // 0=hi,1=lo
            int rem = idx & 1023;
            int row = rem >> 3;
            int ci  = rem & 7;
            const char* src = (const char*)(plane ? g_Wd_lo : g_Wd_hi)
                              + (size_t)row * (DIMSZ * 2) + (size_t)k0 * 2 + ci * 16;
            uint32_t dst = al + bufb + 16384 + (uint32_t)plane * 16384
                           + SWZ((uint32_t)row * 128 + (uint32_t)ci * 16);
            CP_ASYNC16(dst, src);
        }
    };

    // 8 warps: 2(M) x 4(N), warp tile 32x32
    int wm0 = (wid & 1) * 32;
    int wn0 = (wid >> 1) * 32;

    uint32_t a_row = (uint32_t)(l & 15);
    uint32_t a_kb  = (uint32_t)((l >> 4) * 16);
    uint32_t lx    = (uint32_t)((l & 7) * 16);
    uint32_t b_row = (uint32_t)((l >> 4) * 8 + (l & 7));
    uint32_t b_kb  = (uint32_t)(((l >> 3) & 1) * 16);

    float acc[2][4][4];
#pragma unroll
    for (int mt = 0; mt < 2; mt++)
#pragma unroll
        for (int nt = 0; nt < 4; nt++)
#pragma unroll
            for (int j = 0; j < 4; j++) acc[mt][nt][j] = 0.f;

    // prologue
    loadX(0);
    storeX(0);
    loadW(0, 0);
    CP_COMMIT();
    loadX(1);

    for (int c = 0; c < 64; c++) {
        int buf = c & 1;
        CP_WAIT0();
        __syncthreads();
        if (c < 63) {
            loadW(c + 1, buf ^ 1);
            CP_COMMIT();
            storeX(buf ^ 1);
        }
        if (c < 62) loadX(c + 2);

        uint32_t bufb = al + (uint32_t)buf * 49152u;
#pragma unroll
        for (int ks = 0; ks < 4; ks++) {
            uint32_t kso = (uint32_t)ks * 32;
            uint32_t ah[2][4], alo[2][4];
#pragma unroll
            for (int mt = 0; mt < 2; mt++) {
                uint32_t ro = ((uint32_t)(wm0 + mt * 16) + a_row) * 128;
                uint32_t ko = (kso + a_kb) ^ lx;
                ldm4(ah[mt],  bufb + ro + ko);
                ldm4(alo[mt], bufb + 8192 + ro + ko);
            }
            uint32_t bh[2][4], bl[2][4];
#pragma unroll
            for (int pr = 0; pr < 2; pr++) {
                uint32_t ro = ((uint32_t)(wn0 + pr * 16) + b_row) * 128;
                uint32_t ko = (kso + b_kb) ^ lx;
                ldm4(bh[pr], bufb + 16384 + ro + ko);
                ldm4(bl[pr], bufb + 32768 + ro + ko);
            }
#pragma unroll
            for (int mt = 0; mt < 2; mt++)
#pragma unroll
                for (int nt = 0; nt < 4; nt++) {
                    int pr = nt >> 1, of = (nt & 1) * 2;
                    mma_bf16(acc[mt][nt], ah[mt],  bh[pr][of], bh[pr][of + 1]);
                    mma_bf16(acc[mt][nt], ah[mt],  bl[pr][of], bl[pr][of + 1]);
                    mma_bf16(acc[mt][nt], alo[mt], bh[pr][of], bh[pr][of + 1]);
                }
        }
    }

    // ---- sumsq reduce -> rv ----
#pragma unroll
    for (int it = 0; it < 4; it++)
        atomicAdd(((float*)(sal + OFF_SS)) + it * 16 + rsub, ssp[it]);
    __syncthreads();
    if (tid < 64) {
        float rv = rsqrtf(((float*)(sal + OFF_SS))[tid] * (1.0f / 4096.0f) + 1.1920929e-7f);
        ((float*)(sal + OFF_RV))[tid] = rv;
        g_r[m0 + tid] = rv;
    }
    __syncthreads();

    // ---- epilogue: h = silu(rv*acc) -> H hi/lo planes ----
    const float* RV = (const float*)(sal + OFF_RV);
#pragma unroll
    for (int mt = 0; mt < 2; mt++) {
#pragma unroll
        for (int rh = 0; rh < 2; rh++) {
            int row = wm0 + mt * 16 + rh * 8 + (l >> 2);
            float rv = RV[row];
#pragma unroll
            for (int nt = 0; nt < 4; nt++) {
                int col = wn0 + nt * 8 + 2 * (l & 3);
                float z0 = acc[mt][nt][rh * 2 + 0] * rv;
                float z1 = acc[mt][nt][rh * 2 + 1] * rv;
                float h0 = z0 / (1.0f + __expf(-z0));
                float h1 = z1 / (1.0f + __expf(-z1));
                uint32_t p0 = pack_hilo(h0), p1 = pack_hilo(h1);
                size_t o2 = ((size_t)(m0 + row) * RNK + col) * 2;
                *(uint32_t*)((char*)g_H_hi + o2) = (p0 & 0xffffu) | ((p1 & 0xffffu) << 16);
                *(uint32_t*)((char*)g_H_lo + o2) = (p0 >> 16) | (p1 & 0xffff0000u);
            }
        }
    }
}

// ---------------- kernel 2 ----------------
// out = x * r * sigmoid(H @ Wu^T). 256 threads, M=64 x N=128, K=128, 2 CTA/SM.
// smem: AH 16K | AL 16K | BH 32K | BL 32K = 96KB; planes [kc(2)][row][128B].
static constexpr int SMEM2 = 1024 + 98304 + 1024;

__global__ __launch_bounds__(256, 2) void k2_gate(const float* __restrict__ x,
                                                  float* __restrict__ out) {
    extern __shared__ char smem_raw[];
    uint32_t sb = smem_u32(smem_raw);
    uint32_t al = (sb + 1023u) & ~1023u;
    char* sal = smem_raw + (al - sb);
    const uint32_t OFF_RV = 98304;

    int tid = threadIdx.x;
    int wid = tid >> 5;
    int l   = tid & 31;
    int m0  = blockIdx.y * 64;
    int d0  = blockIdx.x * 128;

    // issue all operand cp.asyncs: A 2048 + B 4096 = 6144 16B chunks, 24/thread
#pragma unroll
    for (int i = 0; i < 24; i++) {
        int idx = tid + i * 256;
        const char* src;
        uint32_t dst;
        if (idx < 2048) {            // A = H tile: 64 rows x 16 ci x 2 planes
            int plane = idx >> 10;
            int rem = idx & 1023;
            int row = rem >> 4;
            int ci  = rem & 15;
            src = (const char*)(plane ? g_H_lo : g_H_hi) + (size_t)(m0 + row) * 256 + ci * 16;
            dst = al + (uint32_t)plane * 16384 + (uint32_t)(ci >> 3) * 8192
                  + SWZ((uint32_t)row * 128 + (uint32_t)(ci & 7) * 16);
        } else {                     // B = Wu tile: 128 rows x 16 ci x 2 planes
            int j = idx - 2048;
            int plane = j >> 11;
            int rem = j & 2047;
            int row = rem >> 4;
            int ci  = rem & 15;
            src = (const char*)(plane ? g_Wu_lo : g_Wu_hi) + (size_t)(d0 + row) * 256 + ci * 16;
            dst = al + 32768 + (uint32_t)plane * 32768 + (uint32_t)(ci >> 3) * 16384
                  + SWZ((uint32_t)row * 128 + (uint32_t)(ci & 7) * 16);
        }
        CP_ASYNC16(dst, src);
    }
    CP_COMMIT();

    // warm L2 with this CTA's x tile (epilogue-only data): 256 x 128B lines
    {
        const char* xb = (const char*)(x + (size_t)m0 * DIMSZ + d0);
        int row = tid >> 2;
        PREFETCH_L2(xb + (size_t)row * (DIMSZ * 4) + (tid & 3) * 128);
    }

    if (tid < 64) ((float*)(sal + OFF_RV))[tid] = g_r[m0 + tid];

    // 8 warps: 2(M) x 4(N), warp tile 32x32
    int wm0 = (wid & 1) * 32;
    int wn0 = (wid >> 1) * 32;

    uint32_t a_row = (uint32_t)(l & 15);
    uint32_t a_kb  = (uint32_t)((l >> 4) * 16);
    uint32_t lx    = (uint32_t)((l & 7) * 16);
    uint32_t b_row = (uint32_t)((l >> 4) * 8 + (l & 7));
    uint32_t b_kb  = (uint32_t)(((l >> 3) & 1) * 16);

    float acc[2][4][4];
#pragma unroll
    for (int mt = 0; mt < 2; mt++)
#pragma unroll
        for (int nt = 0; nt < 4; nt++)
#pragma unroll
            for (int j = 0; j < 4; j++) acc[mt][nt][j] = 0.f;

    CP_WAIT0();
    __syncthreads();

#pragma unroll
    for (int kc = 0; kc < 2; kc++) {
#pragma unroll
        for (int ks = 0; ks < 4; ks++) {
            uint32_t kso = (uint32_t)ks * 32;
            uint32_t ah[2][4], alo[2][4];
#pragma unroll
            for (int mt = 0; mt < 2; mt++) {
                uint32_t ro = ((uint32_t)(wm0 + mt * 16) + a_row) * 128;
                uint32_t ko = (kso + a_kb) ^ lx;
                ldm4(ah[mt],  al + (uint32_t)kc * 8192 + ro + ko);
                ldm4(alo[mt], al + 16384 + (uint32_t)kc * 8192 + ro + ko);
            }
            uint32_t bh[2][4], bl[2][4];
#pragma unroll
            for (int pr = 0; pr < 2; pr++) {
                uint32_t ro = ((uint32_t)(wn0 + pr * 16) + b_row) * 128;
                uint32_t ko = (kso + b_kb) ^ lx;
                ldm4(bh[pr], al + 32768 + (uint32_t)kc * 16384 + ro + ko);
                ldm4(bl[pr], al + 65536 + (uint32_t)kc * 16384 + ro + ko);
            }
#pragma unroll
            for (int mt = 0; mt < 2; mt++)
#pragma unroll
                for (int nt = 0; nt < 4; nt++) {
                    int pr = nt >> 1, of = (nt & 1) * 2;
                    mma_bf16(acc[mt][nt], ah[mt],  bh[pr][of], bh[pr][of + 1]);
                    mma_bf16(acc[mt][nt], ah[mt],  bl[pr][of], bl[pr][of + 1]);
                    mma_bf16(acc[mt][nt], alo[mt], bh[pr][of], bh[pr][of + 1]);
                }
        }
    }

    // ---- epilogue: out = x * rv * sigmoid(acc); streaming stores ----
    const float* RV = (const float*)(sal + OFF_RV);
#pragma unroll
    for (int mt = 0; mt < 2; mt++) {
#pragma unroll
        for (int rh = 0; rh < 2; rh++) {
            int row = wm0 + mt * 16 + rh * 8 + (l >> 2);
            float rv = RV[row];
#pragma unroll
            for (int nt = 0; nt < 4; nt++) {
                int col = d0 + wn0 + nt * 8 + 2 * (l & 3);
                float z0 = acc[mt][nt][rh * 2 + 0];
                float z1 = acc[mt][nt][rh * 2 + 1];
                float g0 = 1.0f / (1.0f + __expf(-z0));
                float g1 = 1.0f / (1.0f + __expf(-z1));
                size_t o = (size_t)(m0 + row) * DIMSZ + col;
                float2 xv = *(const float2*)(x + o);
                float2 ov;
                ov.x = xv.x * rv * g0;
                ov.y = xv.y * rv * g1;
                __stcs((float2*)(out + o), ov);
            }
        }
    }
}

// ---------------- launch ----------------
extern "C" void kernel_launch(void* const* d_in, const int* in_sizes, int n_in,
                              void* d_out, int out_size) {
    const float* x  = (const float*)d_in[0];
    const float* Wd = (const float*)d_in[1];
    const float* Wu = (const float*)d_in[2];
    float* out = (float*)d_out;

    cudaFuncSetAttribute(k1_rms_gemm, cudaFuncAttributeMaxDynamicSharedMemorySize, SMEM1);
    cudaFuncSetAttribute(k2_gate,     cudaFuncAttributeMaxDynamicSharedMemorySize, SMEM2);

    kprep<<<(2 * RNK * DIMSZ) / 256, 256>>>(Wd, Wu);
    k1_rms_gemm<<<TOKENS / 64, 256, SMEM1>>>(x);
    k2_gate<<<dim3(DIMSZ / 128, TOKENS / 64), 256, SMEM2>>>(x, out);
}